// round 8
// baseline (speedup 1.0000x reference)
#include <cuda_runtime.h>
#include <cuda_fp16.h>
#include <cstdint>

#define EDIM    512
#define FDIM    2048
#define NCHUNK  32
#define NTOKB   256

__device__ __align__(128) unsigned char g_w2s[4 * NCHUNK * 16384];  // [nb][c][128n x 64k fp16 SW128]
__device__ __align__(128) unsigned char g_w1h[FDIM * 16];           // W1 fp16 [2048 rows][8k = 16B]

#define SWZ(o) ((o) ^ (((o) >> 3) & 0x70))

__device__ __forceinline__ uint32_t smem_u32(const void* p) {
    uint32_t a;
    asm("{ .reg .u64 t; cvta.to.shared.u64 t, %1; cvt.u32.u64 %0, t; }" : "=r"(a) : "l"(p));
    return a;
}
#define MBAR_INIT(a, c) asm volatile("mbarrier.init.shared.b64 [%0], %1;" :: "r"(a), "r"((uint32_t)(c)) : "memory")
#define MBAR_EXPECT(a, n) asm volatile("mbarrier.arrive.expect_tx.shared.b64 _, [%0], %1;" :: "r"(a), "r"((uint32_t)(n)) : "memory")
#define MBAR_ARRIVE(a) asm volatile("mbarrier.arrive.shared.b64 _, [%0];" :: "r"(a) : "memory")
#define MBAR_WAIT(a, ph) do { \
    uint32_t _m = (a), _p = (ph), _d; \
    asm volatile("{ .reg .pred p; mbarrier.try_wait.parity.acquire.cta.shared::cta.b64 p, [%1], %2; selp.b32 %0,1,0,p; }" \
        : "=r"(_d) : "r"(_m), "r"(_p) : "memory"); \
    if (!_d) { \
        asm volatile("{ .reg .pred P1;\nWL_%=:\n mbarrier.try_wait.parity.acquire.cta.shared::cta.b64 P1, [%0], %1, 0x989680;\n @P1 bra.uni WD_%=;\n bra.uni WL_%=;\nWD_%=:\n }" \
            :: "r"(_m), "r"(_p) : "memory"); \
    } } while (0)

__device__ __forceinline__ void bulk_g2s(uint32_t dst, const void* src, uint32_t bytes, uint32_t mbar) {
    asm volatile("cp.async.bulk.shared::cluster.global.mbarrier::complete_tx::bytes [%0], [%1], %2, [%3];"
        :: "r"(dst), "l"(src), "r"(bytes), "r"(mbar) : "memory");
}

#define STS32(a, v)  asm volatile("st.shared.b32 [%0], %1;" :: "r"(a), "r"(v) : "memory")
#define STS128(a, r0, r1, r2, r3) asm volatile("st.shared.v4.b32 [%0], {%1,%2,%3,%4};" :: "r"(a), "r"(r0), "r"(r1), "r"(r2), "r"(r3) : "memory")

#define LDMX4(r, a) asm volatile( \
    "ldmatrix.sync.aligned.m8n8.x4.shared.b16 {%0,%1,%2,%3}, [%4];" \
    : "=r"((r)[0]), "=r"((r)[1]), "=r"((r)[2]), "=r"((r)[3]) : "r"(a))
#define LDMX2(r0, r1, a) asm volatile( \
    "ldmatrix.sync.aligned.m8n8.x2.shared.b16 {%0,%1}, [%2];" \
    : "=r"(r0), "=r"(r1) : "r"(a))
#define MMA16816(cf, a, b0, b1) asm volatile( \
    "mma.sync.aligned.m16n8k16.row.col.f32.f16.f16.f32 " \
    "{%0,%1,%2,%3}, {%4,%5,%6,%7}, {%8,%9}, {%0,%1,%2,%3};" \
    : "+f"((cf)[0]), "+f"((cf)[1]), "+f"((cf)[2]), "+f"((cf)[3]) \
    : "r"((a)[0]), "r"((a)[1]), "r"((a)[2]), "r"((a)[3]), "r"(b0), "r"(b1))
#define MMA1688(c0, c1, c2, c3, a0, a1, b) asm volatile( \
    "mma.sync.aligned.m16n8k8.row.col.f32.f16.f16.f32 " \
    "{%0,%1,%2,%3}, {%4,%5}, {%6}, {%0,%1,%2,%3};" \
    : "+f"(c0), "+f"(c1), "+f"(c2), "+f"(c3) \
    : "r"(a0), "r"(a1), "r"(b))

// ---------------- prep: W2 fp16 swizzled blocks + W1 fp16 rows ----------------
__global__ void prep_all(const float* __restrict__ W2, const float* __restrict__ W1) {
    if (blockIdx.x < 512) {
        int idx = blockIdx.x * 256 + threadIdx.x;
        int n = idx >> 8, g = idx & 255;
        int k0 = g * 8;
        int nb = n >> 7, nl = n & 127;
        int c = k0 >> 6, kl = k0 & 63;
        const float* s = W2 + (size_t)n * FDIM + k0;
        float4 a = *(const float4*)s;
        float4 b = *(const float4*)(s + 4);
        __half2 p0 = __floats2half2_rn(a.x, a.y);
        __half2 p1 = __floats2half2_rn(a.z, a.w);
        __half2 p2 = __floats2half2_rn(b.x, b.y);
        __half2 p3 = __floats2half2_rn(b.z, b.w);
        uint4 v;
        v.x = *reinterpret_cast<uint32_t*>(&p0);
        v.y = *reinterpret_cast<uint32_t*>(&p1);
        v.z = *reinterpret_cast<uint32_t*>(&p2);
        v.w = *reinterpret_cast<uint32_t*>(&p3);
        uint32_t rel = (uint32_t)(nl * 128 + kl * 2);
        *(uint4*)(g_w2s + ((size_t)(nb * NCHUNK + c) << 14) + SWZ(rel)) = v;
    } else {
        int r = (blockIdx.x - 512) * 256 + threadIdx.x;
        if (r < FDIM) {
            float4 a = *(const float4*)(W1 + (size_t)r * 8);
            float4 b = *(const float4*)(W1 + (size_t)r * 8 + 4);
            __half2 p0 = __floats2half2_rn(a.x, a.y);
            __half2 p1 = __floats2half2_rn(a.z, a.w);
            __half2 p2 = __floats2half2_rn(b.x, b.y);
            __half2 p3 = __floats2half2_rn(b.z, b.w);
            uint4 v;
            v.x = *reinterpret_cast<uint32_t*>(&p0);
            v.y = *reinterpret_cast<uint32_t*>(&p1);
            v.z = *reinterpret_cast<uint32_t*>(&p2);
            v.w = *reinterpret_cast<uint32_t*>(&p3);
            *(uint4*)(g_w1h + (size_t)r * 16) = v;
        }
    }
}

// ---------------- fused kernel: GEMM1 (tensor, k8) + GEMM2 (tensor, k16) ----------------
// smem: [0,49152) W2 ring 3x16K; [49152,65536) h tile; [65536,98304) W1 fp16;
//       [98304,106496) b1 f32; [106496,108544) q fp16; [108544,...) mbars
#define SM_STG  0
#define SM_H    49152
#define SM_W1   65536
#define SM_B1   98304
#define SM_Q    106496
#define SM_MB   108544
#define SMEM_F  108608

__global__ void __launch_bounds__(256, 2)
ffq_fused(const float* __restrict__ x, const float* __restrict__ theta,
          const float* __restrict__ b1g, const float* __restrict__ b2,
          float* __restrict__ out) {
    extern __shared__ char smem[];
    const uint32_t sb = smem_u32(smem);
    const int tid = threadIdx.x, wid = tid >> 5, lane = tid & 31;
    const int nb = blockIdx.x, tb = blockIdx.y;
    const int wm = wid & 1, wn = wid >> 1;

    const uint32_t mb_full = sb + SM_MB;        // [3]
    const uint32_t mb_cons = sb + SM_MB + 24;   // [3]
    const uint32_t mb_wl   = sb + SM_MB + 48;

    if (tid == 0) {
#pragma unroll
        for (int s = 0; s < 3; ++s) {
            MBAR_INIT(mb_full + s * 8, 1);
            MBAR_INIT(mb_cons + s * 8, 8);
        }
        MBAR_INIT(mb_wl, 1);
    }
    __syncthreads();
    if (tid == 0) {
        MBAR_EXPECT(mb_wl, 40960);
        bulk_g2s(sb + SM_W1, g_w1h, 32768, mb_wl);
        bulk_g2s(sb + SM_B1, b1g, 8192, mb_wl);
#pragma unroll
        for (int s = 0; s < 3; ++s) {
            MBAR_EXPECT(mb_full + s * 8, 16384);
            bulk_g2s(sb + SM_STG + s * 16384, g_w2s + ((size_t)(nb * NCHUNK + s) << 14), 16384, mb_full + s * 8);
        }
    }

    // q tile: 128 rows x 8 fp16 (16B rows), q = cos(x)*cos(theta)
    if (tid < 128) {
        const int tok = tb * 128 + tid;
        float4 xa = *(const float4*)(x + (size_t)tok * EDIM);
        float4 xb = *(const float4*)(x + (size_t)tok * EDIM + 4);
        float q0 = __cosf(xa.x) * __cosf(__ldg(theta + 0));
        float q1 = __cosf(xa.y) * __cosf(__ldg(theta + 1));
        float q2 = __cosf(xa.z) * __cosf(__ldg(theta + 2));
        float q3 = __cosf(xa.w) * __cosf(__ldg(theta + 3));
        float q4 = __cosf(xb.x) * __cosf(__ldg(theta + 4));
        float q5 = __cosf(xb.y) * __cosf(__ldg(theta + 5));
        float q6 = __cosf(xb.z) * __cosf(__ldg(theta + 6));
        float q7 = __cosf(xb.w) * __cosf(__ldg(theta + 7));
        __half2 h0 = __floats2half2_rn(q0, q1);
        __half2 h1 = __floats2half2_rn(q2, q3);
        __half2 h2 = __floats2half2_rn(q4, q5);
        __half2 h3 = __floats2half2_rn(q6, q7);
        STS128(sb + SM_Q + tid * 16,
               *reinterpret_cast<uint32_t*>(&h0), *reinterpret_cast<uint32_t*>(&h1),
               *reinterpret_cast<uint32_t*>(&h2), *reinterpret_cast<uint32_t*>(&h3));
    }
    MBAR_WAIT(mb_wl, 0);
    __syncthreads();   // q, W1, b1 all ready

    // persistent q a-frag (m16k8) for this warp's 16 h-rows
    uint32_t qa0, qa1;
    LDMX2(qa0, qa1, sb + SM_Q + (wid * 16 + (lane & 15)) * 16);

    float cf[16][4];
#pragma unroll
    for (int f = 0; f < 16; ++f)
#pragma unroll
        for (int i = 0; i < 4; ++i) cf[f][i] = 0.0f;

    const uint32_t arow = (uint32_t)(wm * 64 + (lane & 15));
    const uint32_t abyte = (uint32_t)((lane >> 4) * 16);
    const uint32_t brow = (uint32_t)(wn * 32 + (lane & 7) + ((lane >> 4) & 1) * 8);
    const uint32_t bbyte = (uint32_t)(((lane >> 3) & 1) * 16);
    const int g0 = wid * 16 + (lane >> 2);
    const float* b1s = (const float*)(smem + SM_B1);

    for (int c = 0; c < NCHUNK; ++c) {
        const int buf = c % 3;
        const int ph = (c / 3) & 1;

        // ---- GEMM1: h[128x64] = relu(q @ W1chunk^T + b1chunk), warp owns 16 rows ----
        {
            uint32_t w1f[8];
            LDMX4(w1f + 0, sb + SM_W1 + (uint32_t)(c * 64 + lane) * 16);
            LDMX4(w1f + 4, sb + SM_W1 + (uint32_t)(c * 64 + 32 + lane) * 16);
#pragma unroll
            for (int j = 0; j < 8; ++j) {
                const float2 bp = *(const float2*)(b1s + c * 64 + j * 8 + (lane & 3) * 2);
                float c0 = bp.x, c1 = bp.y, c2 = bp.x, c3 = bp.y;
                MMA1688(c0, c1, c2, c3, qa0, qa1, w1f[j]);
                c0 = fmaxf(c0, 0.0f); c1 = fmaxf(c1, 0.0f);
                c2 = fmaxf(c2, 0.0f); c3 = fmaxf(c3, 0.0f);
                __half2 u0 = __floats2half2_rn(c0, c1);
                __half2 u1 = __floats2half2_rn(c2, c3);
                STS32(sb + SM_H + SWZ((uint32_t)(g0 * 128 + j * 16 + (lane & 3) * 4)),
                      *reinterpret_cast<uint32_t*>(&u0));
                STS32(sb + SM_H + SWZ((uint32_t)((g0 + 8) * 128 + j * 16 + (lane & 3) * 4)),
                      *reinterpret_cast<uint32_t*>(&u1));
            }
        }
        __syncthreads();   // h tile ready

        MBAR_WAIT(mb_full + buf * 8, ph);   // W2 chunk landed
        const uint32_t abase = sb + SM_H;
        const uint32_t bbase = sb + SM_STG + buf * 16384;
#pragma unroll
        for (int k = 0; k < 4; ++k) {
            uint32_t af[4][4], bf[2][4];
#pragma unroll
            for (int mi = 0; mi < 4; ++mi)
                LDMX4(af[mi], abase + SWZ((arow + mi * 16) * 128 + k * 32 + abyte));
#pragma unroll
            for (int bi = 0; bi < 2; ++bi)
                LDMX4(bf[bi], bbase + SWZ((brow + bi * 16) * 128 + k * 32 + bbyte));
#pragma unroll
            for (int mi = 0; mi < 4; ++mi)
#pragma unroll
                for (int ni = 0; ni < 4; ++ni)
                    MMA16816(cf[mi * 4 + ni], af[mi], bf[ni >> 1][(ni & 1) * 2], bf[ni >> 1][(ni & 1) * 2 + 1]);
        }
        __syncwarp();
        if (lane == 0) MBAR_ARRIVE(mb_cons + buf * 8);

        if (tid == 0 && c + 3 < NCHUNK) {
            MBAR_WAIT(mb_cons + buf * 8, ph);
            MBAR_EXPECT(mb_full + buf * 8, 16384);
            bulk_g2s(sb + SM_STG + buf * 16384,
                     g_w2s + ((size_t)(nb * NCHUNK + c + 3) << 14), 16384, mb_full + buf * 8);
        }
        __syncthreads();   // h tile free for next GEMM1
    }

    // epilogue
    const int rowbase = tb * 128 + wm * 64 + (lane >> 2);
    const int colbase = nb * 128 + wn * 32 + (lane & 3) * 2;
#pragma unroll
    for (int mi = 0; mi < 4; ++mi) {
#pragma unroll
        for (int ni = 0; ni < 4; ++ni) {
            const int f = mi * 4 + ni;
            const int col = colbase + ni * 8;
            const float2 bv = *(const float2*)(b2 + col);
            const int r0 = rowbase + mi * 16;
            float2 o0, o1;
            o0.x = cf[f][0] + bv.x; o0.y = cf[f][1] + bv.y;
            o1.x = cf[f][2] + bv.x; o1.y = cf[f][3] + bv.y;
            *(float2*)(out + (size_t)r0 * EDIM + col) = o0;
            *(float2*)(out + (size_t)(r0 + 8) * EDIM + col) = o1;
        }
    }
}

extern "C" void kernel_launch(void* const* d_in, const int* in_sizes, int n_in,
                              void* d_out, int out_size) {
    const float* x     = (const float*)d_in[0];
    const float* theta = (const float*)d_in[1];
    const float* W1    = (const float*)d_in[2];
    const float* b1    = (const float*)d_in[3];
    const float* W2    = (const float*)d_in[4];
    const float* b2    = (const float*)d_in[5];
    float* out = (float*)d_out;

    cudaFuncSetAttribute(ffq_fused, cudaFuncAttributeMaxDynamicSharedMemorySize, SMEM_F);

    prep_all<<<520, 256>>>(W2, W1);
    ffq_fused<<<dim3(4, NTOKB), 256, SMEM_F>>>(x, theta, b1, b2, out);
}

// round 9
// speedup vs baseline: 1.2319x; 1.2319x over previous
#include <cuda_runtime.h>
#include <cuda_fp16.h>
#include <cstdint>

#define EDIM    512
#define FDIM    2048
#define NCHUNK  32
#define NTOKB   256

__device__ __align__(128) unsigned char g_w2s[4 * NCHUNK * 16384];   // [nb][c][128n x 64k fp16 SW128]
__device__ __align__(128) unsigned char g_w1h[FDIM * 16];            // W1 fp16 [2048 rows][8k=16B]
__device__ __align__(128) unsigned char g_h[NTOKB * NCHUNK * 16384]; // [tb][c][128m x 64k fp16 SW128]

#define SWZ(o) ((o) ^ (((o) >> 3) & 0x70))

__device__ __forceinline__ uint32_t smem_u32(const void* p) {
    uint32_t a;
    asm("{ .reg .u64 t; cvta.to.shared.u64 t, %1; cvt.u32.u64 %0, t; }" : "=r"(a) : "l"(p));
    return a;
}
#define MBAR_INIT(a, c) asm volatile("mbarrier.init.shared.b64 [%0], %1;" :: "r"(a), "r"((uint32_t)(c)) : "memory")
#define MBAR_EXPECT(a, n) asm volatile("mbarrier.arrive.expect_tx.shared.b64 _, [%0], %1;" :: "r"(a), "r"((uint32_t)(n)) : "memory")
#define MBAR_ARRIVE(a) asm volatile("mbarrier.arrive.shared.b64 _, [%0];" :: "r"(a) : "memory")
#define MBAR_WAIT(a, ph) do { \
    uint32_t _m = (a), _p = (ph), _d; \
    asm volatile("{ .reg .pred p; mbarrier.try_wait.parity.acquire.cta.shared::cta.b64 p, [%1], %2; selp.b32 %0,1,0,p; }" \
        : "=r"(_d) : "r"(_m), "r"(_p) : "memory"); \
    if (!_d) { \
        asm volatile("{ .reg .pred P1;\nWL_%=:\n mbarrier.try_wait.parity.acquire.cta.shared::cta.b64 P1, [%0], %1, 0x989680;\n @P1 bra.uni WD_%=;\n bra.uni WL_%=;\nWD_%=:\n }" \
            :: "r"(_m), "r"(_p) : "memory"); \
    } } while (0)

__device__ __forceinline__ void bulk_g2s(uint32_t dst, const void* src, uint32_t bytes, uint32_t mbar) {
    asm volatile("cp.async.bulk.shared::cluster.global.mbarrier::complete_tx::bytes [%0], [%1], %2, [%3];"
        :: "r"(dst), "l"(src), "r"(bytes), "r"(mbar) : "memory");
}
__device__ __forceinline__ void bulk_s2g(void* dst, uint32_t src, uint32_t bytes) {
    asm volatile("cp.async.bulk.global.shared::cta.bulk_group [%0], [%1], %2;"
        :: "l"(dst), "r"(src), "r"(bytes) : "memory");
}
#define BULK_COMMIT() asm volatile("cp.async.bulk.commit_group;" ::: "memory")
#define BULK_WAIT(n)  asm volatile("cp.async.bulk.wait_group %0;" :: "n"(n) : "memory")
#define FENCE_ASYNC() asm volatile("fence.proxy.async.shared::cta;" ::: "memory")

#define STS32(a, v)  asm volatile("st.shared.b32 [%0], %1;" :: "r"(a), "r"(v) : "memory")
#define STS128(a, r0, r1, r2, r3) asm volatile("st.shared.v4.b32 [%0], {%1,%2,%3,%4};" :: "r"(a), "r"(r0), "r"(r1), "r"(r2), "r"(r3) : "memory")

#define LDMX4(r, a) asm volatile( \
    "ldmatrix.sync.aligned.m8n8.x4.shared.b16 {%0,%1,%2,%3}, [%4];" \
    : "=r"((r)[0]), "=r"((r)[1]), "=r"((r)[2]), "=r"((r)[3]) : "r"(a))
#define LDMX2(r0, r1, a) asm volatile( \
    "ldmatrix.sync.aligned.m8n8.x2.shared.b16 {%0,%1}, [%2];" \
    : "=r"(r0), "=r"(r1) : "r"(a))
#define MMA16816(cf, a, b0, b1) asm volatile( \
    "mma.sync.aligned.m16n8k16.row.col.f32.f16.f16.f32 " \
    "{%0,%1,%2,%3}, {%4,%5,%6,%7}, {%8,%9}, {%0,%1,%2,%3};" \
    : "+f"((cf)[0]), "+f"((cf)[1]), "+f"((cf)[2]), "+f"((cf)[3]) \
    : "r"((a)[0]), "r"((a)[1]), "r"((a)[2]), "r"((a)[3]), "r"(b0), "r"(b1))
#define MMA1688(c0, c1, c2, c3, a0, a1, b) asm volatile( \
    "mma.sync.aligned.m16n8k8.row.col.f32.f16.f16.f32 " \
    "{%0,%1,%2,%3}, {%4,%5}, {%6}, {%0,%1,%2,%3};" \
    : "+f"(c0), "+f"(c1), "+f"(c2), "+f"(c3) \
    : "r"(a0), "r"(a1), "r"(b))

// ---------------- prep: W2 fp16 swizzled + W1 fp16 rows ----------------
__global__ void prep_all(const float* __restrict__ W2, const float* __restrict__ W1) {
    if (blockIdx.x < 512) {
        int idx = blockIdx.x * 256 + threadIdx.x;
        int n = idx >> 8, g = idx & 255;
        int k0 = g * 8;
        int nb = n >> 7, nl = n & 127;
        int c = k0 >> 6, kl = k0 & 63;
        const float* s = W2 + (size_t)n * FDIM + k0;
        float4 a = *(const float4*)s;
        float4 b = *(const float4*)(s + 4);
        __half2 p0 = __floats2half2_rn(a.x, a.y);
        __half2 p1 = __floats2half2_rn(a.z, a.w);
        __half2 p2 = __floats2half2_rn(b.x, b.y);
        __half2 p3 = __floats2half2_rn(b.z, b.w);
        uint4 v;
        v.x = *reinterpret_cast<uint32_t*>(&p0);
        v.y = *reinterpret_cast<uint32_t*>(&p1);
        v.z = *reinterpret_cast<uint32_t*>(&p2);
        v.w = *reinterpret_cast<uint32_t*>(&p3);
        uint32_t rel = (uint32_t)(nl * 128 + kl * 2);
        *(uint4*)(g_w2s + ((size_t)(nb * NCHUNK + c) << 14) + SWZ(rel)) = v;
    } else {
        int r = (blockIdx.x - 512) * 256 + threadIdx.x;
        if (r < FDIM) {
            float4 a = *(const float4*)(W1 + (size_t)r * 8);
            float4 b = *(const float4*)(W1 + (size_t)r * 8 + 4);
            __half2 p0 = __floats2half2_rn(a.x, a.y);
            __half2 p1 = __floats2half2_rn(a.z, a.w);
            __half2 p2 = __floats2half2_rn(b.x, b.y);
            __half2 p3 = __floats2half2_rn(b.z, b.w);
            uint4 v;
            v.x = *reinterpret_cast<uint32_t*>(&p0);
            v.y = *reinterpret_cast<uint32_t*>(&p1);
            v.z = *reinterpret_cast<uint32_t*>(&p2);
            v.w = *reinterpret_cast<uint32_t*>(&p3);
            *(uint4*)(g_w1h + (size_t)r * 16) = v;
        }
    }
}

// ---------------- kernel A: h via tensor-core GEMM1 ----------------
// smem: [0,32768) W1h; [32768,40960) b1; [40960,43008) q; [43008,75776) 2x h tile; mbar 75776
#define SA_W1  0
#define SA_B1  32768
#define SA_Q   40960
#define SA_HT  43008
#define SA_MB  75776
#define SMEM_A 75840

__global__ void __launch_bounds__(256)
ffq_h(const float* __restrict__ x, const float* __restrict__ theta,
      const float* __restrict__ b1g) {
    extern __shared__ char smem[];
    const uint32_t sb = smem_u32(smem);
    const int tid = threadIdx.x, wid = tid >> 5, lane = tid & 31;
    const int tb = blockIdx.x;

    if (tid == 0) {
        MBAR_INIT(sb + SA_MB, 1);
    }
    __syncthreads();
    if (tid == 0) {
        MBAR_EXPECT(sb + SA_MB, 40960);
        bulk_g2s(sb + SA_W1, g_w1h, 32768, sb + SA_MB);
        bulk_g2s(sb + SA_B1, b1g, 8192, sb + SA_MB);
    }

    // q tile: 128 rows x 8 fp16
    if (tid < 128) {
        const int tok = tb * 128 + tid;
        float4 xa = *(const float4*)(x + (size_t)tok * EDIM);
        float4 xb = *(const float4*)(x + (size_t)tok * EDIM + 4);
        float q0 = __cosf(xa.x) * __cosf(__ldg(theta + 0));
        float q1 = __cosf(xa.y) * __cosf(__ldg(theta + 1));
        float q2 = __cosf(xa.z) * __cosf(__ldg(theta + 2));
        float q3 = __cosf(xa.w) * __cosf(__ldg(theta + 3));
        float q4 = __cosf(xb.x) * __cosf(__ldg(theta + 4));
        float q5 = __cosf(xb.y) * __cosf(__ldg(theta + 5));
        float q6 = __cosf(xb.z) * __cosf(__ldg(theta + 6));
        float q7 = __cosf(xb.w) * __cosf(__ldg(theta + 7));
        __half2 h0 = __floats2half2_rn(q0, q1);
        __half2 h1 = __floats2half2_rn(q2, q3);
        __half2 h2 = __floats2half2_rn(q4, q5);
        __half2 h3 = __floats2half2_rn(q6, q7);
        STS128(sb + SA_Q + tid * 16,
               *reinterpret_cast<uint32_t*>(&h0), *reinterpret_cast<uint32_t*>(&h1),
               *reinterpret_cast<uint32_t*>(&h2), *reinterpret_cast<uint32_t*>(&h3));
    }
    MBAR_WAIT(sb + SA_MB, 0);
    __syncthreads();

    // persistent q a-frag (m16k8) for this warp's 16 rows
    uint32_t qa0, qa1;
    LDMX2(qa0, qa1, sb + SA_Q + (wid * 16 + (lane & 15)) * 16);

    const int g0 = wid * 16 + (lane >> 2);
    const float* b1s = (const float*)(smem + SA_B1);

    for (int c = 0; c < NCHUNK; ++c) {
        const uint32_t hbase = sb + SA_HT + (c & 1) * 16384;
        if (c >= 2) {
            if (tid == 0) BULK_WAIT(1);
            __syncthreads();
        }
        uint32_t w1f[8];
        LDMX4(w1f + 0, sb + SA_W1 + (uint32_t)(c * 64 + lane) * 16);
        LDMX4(w1f + 4, sb + SA_W1 + (uint32_t)(c * 64 + 32 + lane) * 16);
#pragma unroll
        for (int j = 0; j < 8; ++j) {
            const float2 bp = *(const float2*)(b1s + c * 64 + j * 8 + (lane & 3) * 2);
            float c0 = bp.x, c1 = bp.y, c2 = bp.x, c3 = bp.y;
            MMA1688(c0, c1, c2, c3, qa0, qa1, w1f[j]);
            c0 = fmaxf(c0, 0.0f); c1 = fmaxf(c1, 0.0f);
            c2 = fmaxf(c2, 0.0f); c3 = fmaxf(c3, 0.0f);
            __half2 u0 = __floats2half2_rn(c0, c1);
            __half2 u1 = __floats2half2_rn(c2, c3);
            STS32(hbase + SWZ((uint32_t)(g0 * 128 + j * 16 + (lane & 3) * 4)),
                  *reinterpret_cast<uint32_t*>(&u0));
            STS32(hbase + SWZ((uint32_t)((g0 + 8) * 128 + j * 16 + (lane & 3) * 4)),
                  *reinterpret_cast<uint32_t*>(&u1));
        }
        __syncthreads();
        if (tid == 0) {
            FENCE_ASYNC();
            bulk_s2g(g_h + ((size_t)(tb * NCHUNK + c) << 14), hbase, 16384);
            BULK_COMMIT();
        }
    }
    if (tid == 0) BULK_WAIT(0);
}

// ---------------- kernel B: out = h @ W2^T + b2 (R4 proven) ----------------
#define SB_FULL 98304
#define SB_CONS 98328
#define SMEM_B  98368

__global__ void __launch_bounds__(256, 2)
ffq_gemm(const float* __restrict__ b2, float* __restrict__ out) {
    extern __shared__ char smem[];
    const uint32_t sb = smem_u32(smem);
    const int tid = threadIdx.x, wid = tid >> 5, lane = tid & 31;
    const int nb = blockIdx.x, tb = blockIdx.y;
    const int wm = wid & 1, wn = wid >> 1;

    if (tid == 0) {
#pragma unroll
        for (int s = 0; s < 3; ++s) {
            MBAR_INIT(sb + SB_FULL + s * 8, 1);
            MBAR_INIT(sb + SB_CONS + s * 8, 8);
        }
    }
    __syncthreads();

    if (tid == 0) {
#pragma unroll
        for (int s = 0; s < 3; ++s) {
            MBAR_EXPECT(sb + SB_FULL + s * 8, 32768);
            bulk_g2s(sb + s * 32768, g_h + ((size_t)(tb * NCHUNK + s) << 14), 16384, sb + SB_FULL + s * 8);
            bulk_g2s(sb + s * 32768 + 16384, g_w2s + ((size_t)(nb * NCHUNK + s) << 14), 16384, sb + SB_FULL + s * 8);
        }
    }

    float cf[16][4];
#pragma unroll
    for (int f = 0; f < 16; ++f)
#pragma unroll
        for (int i = 0; i < 4; ++i) cf[f][i] = 0.0f;

    const uint32_t arow = (uint32_t)(wm * 64 + (lane & 15));
    const uint32_t abyte = (uint32_t)((lane >> 4) * 16);
    const uint32_t brow = (uint32_t)(wn * 32 + (lane & 7) + ((lane >> 4) & 1) * 8);
    const uint32_t bbyte = (uint32_t)(((lane >> 3) & 1) * 16);

    int buf = 0, ph = 0;
    for (int c = 0; c < NCHUNK; ++c) {
        MBAR_WAIT(sb + SB_FULL + buf * 8, ph);
        const uint32_t abase = sb + buf * 32768;
        const uint32_t bbase = abase + 16384;
#pragma unroll
        for (int k = 0; k < 4; ++k) {
            uint32_t af[4][4], bf[2][4];
#pragma unroll
            for (int mi = 0; mi < 4; ++mi)
                LDMX4(af[mi], abase + SWZ((arow + mi * 16) * 128 + k * 32 + abyte));
#pragma unroll
            for (int bi = 0; bi < 2; ++bi)
                LDMX4(bf[bi], bbase + SWZ((brow + bi * 16) * 128 + k * 32 + bbyte));
#pragma unroll
            for (int mi = 0; mi < 4; ++mi)
#pragma unroll
                for (int ni = 0; ni < 4; ++ni)
                    MMA16816(cf[mi * 4 + ni], af[mi], bf[ni >> 1][(ni & 1) * 2], bf[ni >> 1][(ni & 1) * 2 + 1]);
        }
        __syncwarp();
        if (lane == 0) MBAR_ARRIVE(sb + SB_CONS + buf * 8);

        if (tid == 0 && c + 3 < NCHUNK) {
            const int s = c + 3;
            MBAR_WAIT(sb + SB_CONS + buf * 8, ph);
            MBAR_EXPECT(sb + SB_FULL + buf * 8, 32768);
            bulk_g2s(sb + buf * 32768, g_h + ((size_t)(tb * NCHUNK + s) << 14), 16384, sb + SB_FULL + buf * 8);
            bulk_g2s(sb + buf * 32768 + 16384, g_w2s + ((size_t)(nb * NCHUNK + s) << 14), 16384, sb + SB_FULL + buf * 8);
        }
        if (++buf == 3) { buf = 0; ph ^= 1; }
    }

    const int rowbase = tb * 128 + wm * 64 + (lane >> 2);
    const int colbase = nb * 128 + wn * 32 + (lane & 3) * 2;
#pragma unroll
    for (int mi = 0; mi < 4; ++mi) {
#pragma unroll
        for (int ni = 0; ni < 4; ++ni) {
            const int f = mi * 4 + ni;
            const int col = colbase + ni * 8;
            const float2 bv = *(const float2*)(b2 + col);
            const int r0 = rowbase + mi * 16;
            float2 o0, o1;
            o0.x = cf[f][0] + bv.x; o0.y = cf[f][1] + bv.y;
            o1.x = cf[f][2] + bv.x; o1.y = cf[f][3] + bv.y;
            *(float2*)(out + (size_t)r0 * EDIM + col) = o0;
            *(float2*)(out + (size_t)(r0 + 8) * EDIM + col) = o1;
        }
    }
}

extern "C" void kernel_launch(void* const* d_in, const int* in_sizes, int n_in,
                              void* d_out, int out_size) {
    const float* x     = (const float*)d_in[0];
    const float* theta = (const float*)d_in[1];
    const float* W1    = (const float*)d_in[2];
    const float* b1    = (const float*)d_in[3];
    const float* W2    = (const float*)d_in[4];
    const float* b2    = (const float*)d_in[5];
    float* out = (float*)d_out;

    cudaFuncSetAttribute(ffq_h, cudaFuncAttributeMaxDynamicSharedMemorySize, SMEM_A);
    cudaFuncSetAttribute(ffq_gemm, cudaFuncAttributeMaxDynamicSharedMemorySize, SMEM_B);

    prep_all<<<520, 256>>>(W2, W1);
    ffq_h<<<NTOKB, 256, SMEM_A>>>(x, theta, b1);
    ffq_gemm<<<dim3(4, NTOKB), 256, SMEM_B>>>(b2, out);
}